// round 5
// baseline (speedup 1.0000x reference)
#include <cuda_runtime.h>
#include <cuda_bf16.h>

// BSplineActivation: y = sum_i B_i^3(clip(x,-1,1)) * c_i, uniform 12-knot
// grid, 8 coefficients. Per interval j (0..10) the spline is one cubic.
// Bases+coefficients folded into an 11-entry table of cubics RE-CENTERED at
// t=0.5 so the magic-number floor (u+1.5*2^23) yields both the index bits and
// the fractional offset s = t-0.5 with only FADD/LOP3 (no F2I/I2F, ~40 cycles
// off the per-element dependency chain). Table stored as two float2 arrays ->
// 2x conflict-free LDS.64 per element. Single-wave persistent grid (740 CTAs,
// 5/SM): no wave transitions, no tail quantization. 4 front-batched LDG.128
// per loop iteration (MLP=4).

#define THREADS 256
#define VPT 4            // float4 per thread per iteration
#define MAGIC 12582912.0f  // 1.5 * 2^23

__global__ void __launch_bounds__(THREADS, 5)
bspline_act_kernel(const float* __restrict__ x,
                   const float* __restrict__ grid,
                   const float* __restrict__ coef,
                   float* __restrict__ out,
                   int n4)
{
    __shared__ float2 sA[16];   // {Q0,Q1}  (re-centered at t=0.5)
    __shared__ float2 sB[16];   // {Q2,Q3}
    __shared__ float  sInvH, sC;  // u' = x*invh + sC,  sC = -g0*invh - 0.5

    const int tid = threadIdx.x;

    if (tid < 16) {
        float c0 = 0.f, c1 = 0.f, c2 = 0.f, c3 = 0.f;
        if (tid < 11) {
            int i0 = tid - 3, i1 = tid - 2, i2 = tid - 1, i3 = tid;
            c0 = (i0 >= 0 && i0 < 8) ? __ldg(&coef[i0]) : 0.0f;
            c1 = (i1 >= 0 && i1 < 8) ? __ldg(&coef[i1]) : 0.0f;
            c2 = (i2 >= 0 && i2 < 8) ? __ldg(&coef[i2]) : 0.0f;
            c3 = (i3 >= 0 && i3 < 8) ? __ldg(&coef[i3]) : 0.0f;
        }
        // Cubic in t: P0..P3 (uniform B-spline bases folded with coefs)
        float P0 = (c0 + 4.0f * c1 + c2) * (1.0f / 6.0f);
        float P1 = (c2 - c0) * 0.5f;
        float P2 = (c0 - 2.0f * c1 + c2) * 0.5f;
        float P3 = (c3 - c0 + 3.0f * (c1 - c2)) * (1.0f / 6.0f);
        // Re-center: t = s + 0.5, s in [-0.5, 0.5)
        float Q0 = P0 + 0.5f * P1 + 0.25f * P2 + 0.125f * P3;
        float Q1 = P1 + P2 + 0.75f * P3;
        float Q2 = P2 + 1.5f * P3;
        float Q3 = P3;
        sA[tid] = make_float2(Q0, Q1);
        sB[tid] = make_float2(Q2, Q3);
        if (tid == 0) {
            float g0   = __ldg(&grid[0]);
            float g11  = __ldg(&grid[11]);
            float invh = 11.0f / (g11 - g0);
            sInvH = invh;
            sC    = -g0 * invh - 0.5f;
        }
    }
    __syncthreads();

    const float invh = sInvH;
    const float cadd = sC;

    const float4* __restrict__ x4 = (const float4*)x;
    float4* __restrict__ o4 = (float4*)out;

    const int stride = gridDim.x * THREADS;   // float4 per q-slot
    const int chunk  = stride * VPT;

    for (int idx = blockIdx.x * THREADS + tid; idx < n4; idx += chunk) {
        // Front-batched loads: up to 4 independent LDG.128 in flight.
        float4 v[VPT];
        #pragma unroll
        for (int q = 0; q < VPT; q++) {
            int i = idx + q * stride;
            if (i < n4) v[q] = x4[i];
        }

        #pragma unroll
        for (int q = 0; q < VPT; q++) {
            float4 r;
            #pragma unroll
            for (int k = 0; k < 4; k++) {
                float xv = (k == 0) ? v[q].x : (k == 1) ? v[q].y
                         : (k == 2) ? v[q].z : v[q].w;
                float xc = fminf(fmaxf(xv, -1.0f), 1.0f);
                float u  = fmaf(xc, invh, cadd);   // in [0.417, 9.583]
                float f  = u + MAGIC;              // mantissa low bits = round(u)
                float jf = f - MAGIC;              // round(u) as float
                float s  = u - jf;                 // in [-0.5, 0.5]
                int   j  = (int)(__float_as_uint(f) & 15u);  // = floor of orig u
                float2 A = sA[j];
                float2 B = sB[j];
                float y  = fmaf(fmaf(fmaf(B.y, s, B.x), s, A.y), s, A.x);
                if (k == 0) r.x = y; else if (k == 1) r.y = y;
                else if (k == 2) r.z = y; else r.w = y;
            }
            int i = idx + q * stride;
            if (i < n4) o4[i] = r;
        }
    }
}

// Scalar tail kernel for n % 4 != 0 (not hit for 2048x4096).
__global__ void bspline_tail_kernel(const float* __restrict__ x,
                                    const float* __restrict__ grid,
                                    const float* __restrict__ coef,
                                    float* __restrict__ out,
                                    int start, int n)
{
    int idx = start + threadIdx.x;
    if (idx >= n) return;
    float g0  = grid[0];
    float invh = 11.0f / (grid[11] - g0);
    float xc = fminf(fmaxf(x[idx], -1.0f), 1.0f);
    float u  = (xc - g0) * invh;
    int   j  = min(max((int)u, 0), 10);
    float t  = u - (float)j;
    int i0 = j - 3, i1 = j - 2, i2 = j - 1, i3 = j;
    float c0 = (i0 >= 0 && i0 < 8) ? coef[i0] : 0.0f;
    float c1 = (i1 >= 0 && i1 < 8) ? coef[i1] : 0.0f;
    float c2 = (i2 >= 0 && i2 < 8) ? coef[i2] : 0.0f;
    float c3 = (i3 >= 0 && i3 < 8) ? coef[i3] : 0.0f;
    float p0 = (c0 + 4.0f * c1 + c2) * (1.0f / 6.0f);
    float p1 = (c2 - c0) * 0.5f;
    float p2 = (c0 - 2.0f * c1 + c2) * 0.5f;
    float p3 = (c3 - c0 + 3.0f * (c1 - c2)) * (1.0f / 6.0f);
    out[idx] = fmaf(fmaf(fmaf(p3, t, p2), t, p1), t, p0);
}

extern "C" void kernel_launch(void* const* d_in, const int* in_sizes, int n_in,
                              void* d_out, int out_size)
{
    const float* x    = (const float*)d_in[0];   // [2048*4096] fp32
    const float* grid = (const float*)d_in[1];   // [12] fp32
    const float* coef = (const float*)d_in[2];   // [8] fp32
    float* out = (float*)d_out;

    const int n  = in_sizes[0];
    const int n4 = n >> 2;

    // Single wave: 5 CTAs/SM x 148 SMs.
    int per_block = THREADS * VPT;
    int need = (n4 + per_block - 1) / per_block;
    int blocks = need < 740 ? need : 740;
    if (blocks < 1) blocks = 1;

    bspline_act_kernel<<<blocks, THREADS>>>(x, grid, coef, out, n4);

    const int rem = n & 3;
    if (rem) {
        bspline_tail_kernel<<<1, 4>>>(x, grid, coef, out, n4 << 2, n);
    }
}